// round 2
// baseline (speedup 1.0000x reference)
#include <cuda_runtime.h>
#include <cuda_bf16.h>
#include <math_constants.h>

#define NV 8192
#define NF 16384
#define NP 16384
#define NSPLIT 16
#define TILE 256
#define FPS (NF / NSPLIT)   // 1024 triangles per split

// Packed per-triangle data: ax,ay,az, bx,by,bz, cx,cy,cz, nx,ny,nz
__device__ __align__(16) float g_tri[NF * 12];
// Partial results per (split, point): {dist2, sign_dot}
__device__ float2 g_partial[NSPLIT * NP];

// Strict IEEE helpers (never FMA-contracted). Reduction order matches XLA's
// left-to-right 3-element einsum: ((x0*y0 + x1*y1) + x2*y2)
__device__ __forceinline__ float dot3(float x0, float x1, float x2,
                                      float y0, float y1, float y2) {
    return __fadd_rn(__fadd_rn(__fmul_rn(x0, y0), __fmul_rn(x1, y1)),
                     __fmul_rn(x2, y2));
}

__device__ __forceinline__ float sdiv(float x, float y) {
    return __fdiv_rn(x, (y == 0.0f) ? 1.0f : y);
}

__global__ void precompute_tris(const float* __restrict__ vertices,
                                const int* __restrict__ faces) {
    int f = blockIdx.x * blockDim.x + threadIdx.x;
    if (f >= NF) return;
    int i0 = faces[f * 3 + 0];
    int i1 = faces[f * 3 + 1];
    int i2 = faces[f * 3 + 2];
    float ax = vertices[i0 * 3 + 0], ay = vertices[i0 * 3 + 1], az = vertices[i0 * 3 + 2];
    float bx = vertices[i1 * 3 + 0], by = vertices[i1 * 3 + 1], bz = vertices[i1 * 3 + 2];
    float cx = vertices[i2 * 3 + 0], cy = vertices[i2 * 3 + 1], cz = vertices[i2 * 3 + 2];
    float abx = __fsub_rn(bx, ax), aby = __fsub_rn(by, ay), abz = __fsub_rn(bz, az);
    float acx = __fsub_rn(cx, ax), acy = __fsub_rn(cy, ay), acz = __fsub_rn(cz, az);
    // nrm = cross(ab, ac), strict mul/sub
    float nx = __fsub_rn(__fmul_rn(aby, acz), __fmul_rn(abz, acy));
    float ny = __fsub_rn(__fmul_rn(abz, acx), __fmul_rn(abx, acz));
    float nz = __fsub_rn(__fmul_rn(abx, acy), __fmul_rn(aby, acx));
    float* t = &g_tri[f * 12];
    t[0] = ax; t[1] = ay; t[2] = az;
    t[3] = bx; t[4] = by; t[5] = bz;
    t[6] = cx; t[7] = cy; t[8] = cz;
    t[9] = nx; t[10] = ny; t[11] = nz;
}

__global__ void __launch_bounds__(256) sdf_partial(const float* __restrict__ points) {
    int pidx = blockIdx.x * 256 + threadIdx.x;
    float px = points[pidx * 3 + 0];
    float py = points[pidx * 3 + 1];
    float pz = points[pidx * 3 + 2];

    __shared__ float4 smem[TILE * 3];

    int fbase = blockIdx.y * FPS;
    float best = CUDART_INF_F;
    float sd = 0.0f;

    for (int t0 = 0; t0 < FPS; t0 += TILE) {
        const float4* gsrc = reinterpret_cast<const float4*>(&g_tri[(fbase + t0) * 12]);
        #pragma unroll
        for (int k = 0; k < 3; k++) {
            smem[threadIdx.x + k * 256] = gsrc[threadIdx.x + k * 256];
        }
        __syncthreads();

        #pragma unroll 4
        for (int j = 0; j < TILE; j++) {
            float4 q0 = smem[j * 3 + 0];
            float4 q1 = smem[j * 3 + 1];
            float4 q2 = smem[j * 3 + 2];
            float ax = q0.x, ay = q0.y, az = q0.z;
            float bx = q0.w, by = q1.x, bz = q1.y;
            float cx = q1.z, cy = q1.w, cz = q2.x;
            float nx = q2.y, ny = q2.z, nz = q2.w;

            float abx = __fsub_rn(bx, ax), aby = __fsub_rn(by, ay), abz = __fsub_rn(bz, az);
            float acx = __fsub_rn(cx, ax), acy = __fsub_rn(cy, ay), acz = __fsub_rn(cz, az);
            float apx = __fsub_rn(px, ax), apy = __fsub_rn(py, ay), apz = __fsub_rn(pz, az);
            float bpx = __fsub_rn(px, bx), bpy = __fsub_rn(py, by), bpz = __fsub_rn(pz, bz);
            float cpx = __fsub_rn(px, cx), cpy = __fsub_rn(py, cy), cpz = __fsub_rn(pz, cz);

            float d1 = dot3(abx, aby, abz, apx, apy, apz);
            float d2 = dot3(acx, acy, acz, apx, apy, apz);
            float d3 = dot3(abx, aby, abz, bpx, bpy, bpz);
            float d4 = dot3(acx, acy, acz, bpx, bpy, bpz);
            float d5 = dot3(abx, aby, abz, cpx, cpy, cpz);
            float d6 = dot3(acx, acy, acz, cpx, cpy, cpz);

            float va = __fsub_rn(__fmul_rn(d3, d6), __fmul_rn(d5, d4));
            float vb = __fsub_rn(__fmul_rn(d5, d2), __fmul_rn(d1, d6));
            float vc = __fsub_rn(__fmul_rn(d1, d4), __fmul_rn(d3, d2));
            float denom = __fadd_rn(__fadd_rn(va, vb), vc);
            float v = sdiv(vb, denom);
            float w = sdiv(vc, denom);

            float e43 = __fsub_rn(d4, d3);
            float e56 = __fsub_rn(d5, d6);
            float t_bc = sdiv(e43, __fadd_rn(e43, e56));
            if (va <= 0.0f && e43 >= 0.0f && e56 >= 0.0f) {
                v = __fsub_rn(1.0f, t_bc); w = t_bc;
            }
            float t_ac = sdiv(d2, __fsub_rn(d2, d6));
            if (vb <= 0.0f && d2 >= 0.0f && d6 <= 0.0f) { v = 0.0f; w = t_ac; }
            float t_ab = sdiv(d1, __fsub_rn(d1, d3));
            if (vc <= 0.0f && d1 >= 0.0f && d3 <= 0.0f) { v = t_ab; w = 0.0f; }
            if (d6 >= 0.0f && d5 <= d6) { v = 0.0f; w = 1.0f; }
            if (d3 >= 0.0f && d4 <= d3) { v = 1.0f; w = 0.0f; }
            if (d1 <= 0.0f && d2 <= 0.0f) { v = 0.0f; w = 0.0f; }

            // closest = (a + v*ab) + w*ac, strict order
            float clx = __fadd_rn(__fadd_rn(ax, __fmul_rn(v, abx)), __fmul_rn(w, acx));
            float cly = __fadd_rn(__fadd_rn(ay, __fmul_rn(v, aby)), __fmul_rn(w, acy));
            float clz = __fadd_rn(__fadd_rn(az, __fmul_rn(v, abz)), __fmul_rn(w, acz));
            float dx = __fsub_rn(px, clx);
            float dy = __fsub_rn(py, cly);
            float dz = __fsub_rn(pz, clz);
            float dist2 = dot3(dx, dy, dz, dx, dy, dz);
            if (dist2 < best) {
                best = dist2;
                sd = dot3(dx, dy, dz, nx, ny, nz);
            }
        }
        __syncthreads();
    }

    g_partial[blockIdx.y * NP + pidx] = make_float2(best, sd);
}

__global__ void sdf_reduce(float* __restrict__ out) {
    int i = blockIdx.x * blockDim.x + threadIdx.x;
    if (i >= NP) return;
    float best = CUDART_INF_F;
    float sd = 0.0f;
    #pragma unroll
    for (int s = 0; s < NSPLIT; s++) {
        float2 v = g_partial[s * NP + i];
        if (v.x < best) { best = v.x; sd = v.y; }
    }
    float dist = sqrtf(fmaxf(best, 1e-12f));
    out[i] = (sd > 0.0f) ? -dist : dist;
}

extern "C" void kernel_launch(void* const* d_in, const int* in_sizes, int n_in,
                              void* d_out, int out_size) {
    const float* points   = (const float*)d_in[0];
    const float* vertices = (const float*)d_in[1];
    const int*   faces    = (const int*)d_in[2];
    float* out = (float*)d_out;

    precompute_tris<<<(NF + 255) / 256, 256>>>(vertices, faces);
    sdf_partial<<<dim3(NP / 256, NSPLIT), 256>>>(points);
    sdf_reduce<<<(NP + 255) / 256, 256>>>(out);
}